// round 1
// baseline (speedup 1.0000x reference)
#include <cuda_runtime.h>
#include <cuda_bf16.h>
#include <math_constants.h>

// Problem constants
#define B_  64
#define D_  1500
#define T_  1000
#define DA_ 512

// GEMM tile config
#define BT 128   // t rows per CTA
#define BA 128   // a cols per CTA
#define BK 8     // k tile

// Scratch: partial scores per (b, a-split, t). 64*4*1024 floats = 1 MB.
__device__ float g_spart[B_ * 4 * 1024];

// ---------------------------------------------------------------------------
// Kernel 1: fused score GEMM.
// For each (b, t): score = sum_a relu( sum_d x[b,d,t]*w1[d,a] + b1[a] ) * w2[a]
// Each CTA: one (b, t-tile of 128, a-split of 128). Writes partial score over
// its 128 a's to g_spart[b][asplit][t].
// ---------------------------------------------------------------------------
__global__ __launch_bounds__(256, 2)
void k_score(const float* __restrict__ x, const float* __restrict__ w1,
             const float* __restrict__ b1, const float* __restrict__ w2)
{
    const int tt = blockIdx.x;   // 0..7   t tile
    const int as = blockIdx.y;   // 0..3   a split
    const int b  = blockIdx.z;   // 0..63
    const int t0 = tt * BT;
    const int a0 = as * BA;
    const float* xb = x + (size_t)b * D_ * T_;

    __shared__ __align__(16) float As[2][BK][BT];   // [k][t]
    __shared__ __align__(16) float Bs[2][BK][BA];   // [k][a]
    __shared__ float red[BT][17];

    const int tid = threadIdx.x;
    const int lr  = tid >> 5;           // 0..7  (k row for loads)
    const int lc  = (tid & 31) << 2;    // 0..124 step 4 (col for loads)
    const int ty  = tid >> 4;           // 0..15
    const int tx  = tid & 15;           // 0..15

    float acc[8][8];
#pragma unroll
    for (int i = 0; i < 8; i++)
#pragma unroll
        for (int j = 0; j < 8; j++) acc[i][j] = 0.f;

    const int nk = (D_ + BK - 1) / BK;   // 188

    // prologue: tile 0
    {
        float4 va = make_float4(0.f, 0.f, 0.f, 0.f);
        float4 vb = make_float4(0.f, 0.f, 0.f, 0.f);
        int k = lr;
        int t = t0 + lc;
        if (k < D_ && t < T_) va = *reinterpret_cast<const float4*>(xb + (size_t)k * T_ + t);
        if (k < D_)           vb = *reinterpret_cast<const float4*>(w1 + (size_t)k * DA_ + a0 + lc);
        *reinterpret_cast<float4*>(&As[0][lr][lc]) = va;
        *reinterpret_cast<float4*>(&Bs[0][lr][lc]) = vb;
    }
    __syncthreads();

    for (int kt = 0; kt < nk; kt++) {
        const int buf = kt & 1;
        if (kt + 1 < nk) {
            const int k0 = (kt + 1) * BK;
            float4 va = make_float4(0.f, 0.f, 0.f, 0.f);
            float4 vb = make_float4(0.f, 0.f, 0.f, 0.f);
            int k = k0 + lr;
            int t = t0 + lc;
            if (k < D_ && t < T_) va = *reinterpret_cast<const float4*>(xb + (size_t)k * T_ + t);
            if (k < D_)           vb = *reinterpret_cast<const float4*>(w1 + (size_t)k * DA_ + a0 + lc);
            *reinterpret_cast<float4*>(&As[buf ^ 1][lr][lc]) = va;
            *reinterpret_cast<float4*>(&Bs[buf ^ 1][lr][lc]) = vb;
        }
#pragma unroll
        for (int kk = 0; kk < BK; kk++) {
            float af[8], bf[8];
            *reinterpret_cast<float4*>(af)     = *reinterpret_cast<const float4*>(&As[buf][kk][ty * 8]);
            *reinterpret_cast<float4*>(af + 4) = *reinterpret_cast<const float4*>(&As[buf][kk][ty * 8 + 4]);
            *reinterpret_cast<float4*>(bf)     = *reinterpret_cast<const float4*>(&Bs[buf][kk][tx * 8]);
            *reinterpret_cast<float4*>(bf + 4) = *reinterpret_cast<const float4*>(&Bs[buf][kk][tx * 8 + 4]);
#pragma unroll
            for (int i = 0; i < 8; i++)
#pragma unroll
                for (int j = 0; j < 8; j++)
                    acc[i][j] = fmaf(af[i], bf[j], acc[i][j]);
        }
        __syncthreads();
    }

    // Epilogue: relu(h + b1) * w2, reduce over this CTA's 128 a's.
    float b1v[8], w2v[8];
#pragma unroll
    for (int j = 0; j < 8; j++) {
        int a = a0 + tx * 8 + j;
        b1v[j] = b1[a];
        w2v[j] = w2[a];
    }
    float s[8];
#pragma unroll
    for (int i = 0; i < 8; i++) {
        float acc_s = 0.f;
#pragma unroll
        for (int j = 0; j < 8; j++) {
            float h = acc[i][j] + b1v[j];
            h = h > 0.f ? h : 0.f;
            acc_s = fmaf(h, w2v[j], acc_s);
        }
        s[i] = acc_s;
    }
#pragma unroll
    for (int i = 0; i < 8; i++) red[ty * 8 + i][tx] = s[i];
    __syncthreads();
    if (tid < BT) {
        float tot = 0.f;
#pragma unroll
        for (int c = 0; c < 16; c++) tot += red[tid][c];
        int t = t0 + tid;
        if (t < T_) g_spart[((size_t)b * 4 + as) * 1024 + t] = tot;
    }
}

// ---------------------------------------------------------------------------
// Kernel 2: per-batch softmax over T. 64 blocks x 1024 threads.
// Sums the 4 a-split partials (deterministic), softmaxes, writes A to d_out.
// (bias_2 is a scalar shift -> softmax-invariant, omitted.)
// ---------------------------------------------------------------------------
__device__ __forceinline__ float warpMax(float v) {
#pragma unroll
    for (int o = 16; o; o >>= 1) v = fmaxf(v, __shfl_xor_sync(0xffffffffu, v, o));
    return v;
}
__device__ __forceinline__ float warpSum(float v) {
#pragma unroll
    for (int o = 16; o; o >>= 1) v += __shfl_xor_sync(0xffffffffu, v, o);
    return v;
}

__global__ void k_softmax(float* __restrict__ Aout)
{
    const int b = blockIdx.x;
    const int tid = threadIdx.x;          // 0..1023
    const int lane = tid & 31, wid = tid >> 5;
    __shared__ float sm[32];
    __shared__ float bcast;

    const bool valid = tid < T_;
    float sc = 0.f;
    if (valid) {
        const size_t base = (size_t)b * 4 * 1024 + tid;
        sc = g_spart[base] + g_spart[base + 1024] + g_spart[base + 2048] + g_spart[base + 3072];
    }

    // block max
    float v = valid ? sc : -CUDART_INF_F;
    v = warpMax(v);
    if (lane == 0) sm[wid] = v;
    __syncthreads();
    if (wid == 0) {
        float w = (lane < 32) ? sm[lane] : -CUDART_INF_F;
        w = warpMax(w);
        if (lane == 0) bcast = w;
    }
    __syncthreads();
    const float m = bcast;

    float e = valid ? expf(sc - m) : 0.f;
    float ssum = warpSum(e);
    if (lane == 0) sm[wid] = ssum;
    __syncthreads();
    if (wid == 0) {
        float w = (lane < 32) ? sm[lane] : 0.f;
        w = warpSum(w);
        if (lane == 0) bcast = w;
    }
    __syncthreads();
    const float denom = bcast;

    if (valid) Aout[(size_t)b * T_ + tid] = e / denom;
}

// ---------------------------------------------------------------------------
// Kernel 3: weighted stats. E[b,d] = sum_t x*A ; sq = sum_t x^2*A ;
// std = sqrt(relu(sq - E^2) + 1e-5). One warp per d-row, 8 rows per block.
// ---------------------------------------------------------------------------
__global__ __launch_bounds__(256)
void k_stats(const float* __restrict__ x, const float* __restrict__ Ain,
             float* __restrict__ out)
{
    __shared__ __align__(16) float sA[1000];
    const int b  = blockIdx.y;
    const int d0 = blockIdx.x * 8;

    for (int i = threadIdx.x; i < T_; i += blockDim.x) sA[i] = Ain[(size_t)b * T_ + i];
    __syncthreads();

    const int w = threadIdx.x >> 5, lane = threadIdx.x & 31;
    const int d = d0 + w;
    if (d >= D_) return;

    const float* row = x + ((size_t)b * D_ + d) * T_;
    float e = 0.f, q = 0.f;
#pragma unroll
    for (int j = 0; j < 8; j++) {
        int idx = j * 128 + lane * 4;
        if (idx < T_) {
            float4 xv = *reinterpret_cast<const float4*>(row + idx);
            float4 av = *reinterpret_cast<const float4*>(&sA[idx]);
            e = fmaf(xv.x, av.x, e); q = fmaf(xv.x * xv.x, av.x, q);
            e = fmaf(xv.y, av.y, e); q = fmaf(xv.y * xv.y, av.y, q);
            e = fmaf(xv.z, av.z, e); q = fmaf(xv.z * xv.z, av.z, q);
            e = fmaf(xv.w, av.w, e); q = fmaf(xv.w * xv.w, av.w, q);
        }
    }
    e = warpSum(e);
    q = warpSum(q);
    if (lane == 0) {
        float var = q - e * e;
        var = var > 0.f ? var : 0.f;
        out[(size_t)b * 3000 + d]        = e;
        out[(size_t)b * 3000 + 1500 + d] = sqrtf(var + 1e-5f);
    }
}

// ---------------------------------------------------------------------------
// Launcher. Inputs (metadata order): input_feature, w_1, bias_1, w_2, bias_2.
// Output: [A (64*1000) | layer_out (64*3000)] fp32, 256000 elements.
// ---------------------------------------------------------------------------
extern "C" void kernel_launch(void* const* d_in, const int* in_sizes, int n_in,
                              void* d_out, int out_size)
{
    const float* x  = (const float*)d_in[0];
    const float* w1 = (const float*)d_in[1];
    const float* b1 = (const float*)d_in[2];
    const float* w2 = (const float*)d_in[3];
    // d_in[4] = bias_2: softmax-invariant scalar, does not affect A or layer_out.

    float* A_out = (float*)d_out;            // [64, 1000]
    float* L_out = (float*)d_out + B_ * T_;  // [64, 3000]

    dim3 g1(8, 4, B_);
    k_score<<<g1, 256>>>(x, w1, b1, w2);

    k_softmax<<<B_, 1024>>>(A_out);

    dim3 g3((D_ + 7) / 8, B_);
    k_stats<<<g3, 256>>>(x, A_out, L_out);
}

// round 3
// speedup vs baseline: 1.3983x; 1.3983x over previous
#include <cuda_runtime.h>
#include <cuda_bf16.h>
#include <math_constants.h>
#include <cstdint>

// Problem constants
#define B_  64
#define D_  1500
#define T_  1000
#define DA_ 512

#define NKC 47           // K chunks of 32 d (47*32 = 1504 >= 1500)
#define NNC 4            // N chunks of 128 a
#define TILE_BYTES 8192  // 128 rows x 32 bf16 (64B/row)
#define ROW_PITCH 80     // smem row pitch (bank-conflict-free, 16B-aligned)
#define TILE_SMEM (128 * ROW_PITCH)   // 10240
#define BUF_BYTES (4 * TILE_SMEM)     // Ah,Al,Bh,Bl = 40960
#define SMEM_TOTAL (5120 + 2 * BUF_BYTES)  // 87040

// ===========================================================================
// Scratch (__device__ globals — allocation-guard-safe)
// ===========================================================================
__device__ unsigned char g_xp[2][B_][8][NKC][TILE_BYTES];   // x^T hi/lo tiles
__device__ unsigned char g_wp[2][NNC][NKC][TILE_BYTES];     // w1^T hi/lo tiles
__device__ float g_scores[B_ * 1024];

// ===========================================================================
// Helpers
// ===========================================================================
__device__ __forceinline__ uint32_t smem_u32(const void* p) {
    uint32_t a;
    asm("{ .reg .u64 t; cvta.to.shared.u64 t, %1; cvt.u32.u64 %0, t; }" : "=r"(a) : "l"(p));
    return a;
}
__device__ __forceinline__ void cpa16(uint32_t dst, const void* src) {
    asm volatile("cp.async.cg.shared.global [%0], [%1], 16;" :: "r"(dst), "l"(src));
}
#define CP_COMMIT() asm volatile("cp.async.commit_group;" ::: "memory")

__device__ __forceinline__ void mma_bf16(float c[4], const uint32_t a[4],
                                         uint32_t b0, uint32_t b1) {
    asm volatile(
        "mma.sync.aligned.m16n8k16.row.col.f32.bf16.bf16.f32 "
        "{%0,%1,%2,%3}, {%4,%5,%6,%7}, {%8,%9}, {%0,%1,%2,%3};"
        : "+f"(c[0]), "+f"(c[1]), "+f"(c[2]), "+f"(c[3])
        : "r"(a[0]), "r"(a[1]), "r"(a[2]), "r"(a[3]), "r"(b0), "r"(b1));
}

__device__ __forceinline__ void split_pack(float v0, float v1, uint32_t& hi, uint32_t& lo) {
    __nv_bfloat16 h0 = __float2bfloat16(v0), h1 = __float2bfloat16(v1);
    __nv_bfloat16 l0 = __float2bfloat16(v0 - __bfloat162float(h0));
    __nv_bfloat16 l1 = __float2bfloat16(v1 - __bfloat162float(h1));
    hi = (uint32_t)__bfloat16_as_ushort(h0) | ((uint32_t)__bfloat16_as_ushort(h1) << 16);
    lo = (uint32_t)__bfloat16_as_ushort(l0) | ((uint32_t)__bfloat16_as_ushort(l1) << 16);
}

// ===========================================================================
// Prep x: [b][d][t] fp32 -> hi/lo bf16 tiles [b][tt][kc][t(128)][d(32)]
// ===========================================================================
__global__ __launch_bounds__(256)
void k_prep_x(const float* __restrict__ x)
{
    __shared__ float st[32][132];
    const int tt = blockIdx.x, b = blockIdx.y;
    const int tid = threadIdx.x, wid = tid >> 5, lane = tid & 31;
    const float* xb = x + (size_t)b * D_ * T_;

    for (int kc = 0; kc < NKC; kc++) {
        // stage [32 d][128 t] coalesced
#pragma unroll
        for (int i = 0; i < 4; i++) {
            const int dr = i * 8 + wid;
            const int d  = kc * 32 + dr;
            const int t  = tt * 128 + lane * 4;
            float4 v = make_float4(0.f, 0.f, 0.f, 0.f);
            if (d < D_ && t < T_) v = *(const float4*)(xb + (size_t)d * T_ + t);
            *(float4*)&st[dr][lane * 4] = v;
        }
        __syncthreads();
        // transpose + split: thread -> (row t = tid>>1, d-half = tid&1)
        {
            const int t = tid >> 1, h = tid & 1;
            uint32_t hi[8], lo[8];
#pragma unroll
            for (int i = 0; i < 8; i++)
                split_pack(st[h * 16 + i * 2][t], st[h * 16 + i * 2 + 1][t], hi[i], lo[i]);
            unsigned char* dh = g_xp[0][b][tt][kc] + t * 64 + h * 32;
            unsigned char* dl = g_xp[1][b][tt][kc] + t * 64 + h * 32;
            *(uint4*)dh        = make_uint4(hi[0], hi[1], hi[2], hi[3]);
            *(uint4*)(dh + 16) = make_uint4(hi[4], hi[5], hi[6], hi[7]);
            *(uint4*)dl        = make_uint4(lo[0], lo[1], lo[2], lo[3]);
            *(uint4*)(dl + 16) = make_uint4(lo[4], lo[5], lo[6], lo[7]);
        }
        __syncthreads();
    }
}

// ===========================================================================
// Prep w1: [d][a] fp32 -> hi/lo bf16 tiles [nc][kc][n(128)][d(32)]
// ===========================================================================
__global__ __launch_bounds__(256)
void k_prep_w(const float* __restrict__ w1)
{
    __shared__ float st[32][132];
    const int nc = blockIdx.x, kc = blockIdx.y;
    const int tid = threadIdx.x, wid = tid >> 5, lane = tid & 31;

#pragma unroll
    for (int i = 0; i < 4; i++) {
        const int dr = i * 8 + wid;
        const int d  = kc * 32 + dr;
        const int n  = nc * 128 + lane * 4;
        float4 v = make_float4(0.f, 0.f, 0.f, 0.f);
        if (d < D_) v = *(const float4*)(w1 + (size_t)d * DA_ + n);
        *(float4*)&st[dr][lane * 4] = v;
    }
    __syncthreads();
    {
        const int n = tid >> 1, h = tid & 1;
        uint32_t hi[8], lo[8];
#pragma unroll
        for (int i = 0; i < 8; i++)
            split_pack(st[h * 16 + i * 2][n], st[h * 16 + i * 2 + 1][n], hi[i], lo[i]);
        unsigned char* dh = g_wp[0][nc][kc] + n * 64 + h * 32;
        unsigned char* dl = g_wp[1][nc][kc] + n * 64 + h * 32;
        *(uint4*)dh        = make_uint4(hi[0], hi[1], hi[2], hi[3]);
        *(uint4*)(dh + 16) = make_uint4(hi[4], hi[5], hi[6], hi[7]);
        *(uint4*)dl        = make_uint4(lo[0], lo[1], lo[2], lo[3]);
        *(uint4*)(dl + 16) = make_uint4(lo[4], lo[5], lo[6], lo[7]);
    }
}

// ===========================================================================
// k_score_mma: per CTA (b, 128-t tile) -> scores[t] via split-bf16 HMMA.
// ===========================================================================
__global__ __launch_bounds__(256, 2)
void k_score_mma(const float* __restrict__ b1, const float* __restrict__ w2)
{
    extern __shared__ __align__(16) unsigned char smem[];
    float2* bw  = (float2*)smem;                 // [512] (b1, w2) interleaved
    float*  red = (float*)(smem + 4096);         // [2][128]
    unsigned char* bufs = smem + 5120;           // double buffer

    const int tid = threadIdx.x;
    const int wid = tid >> 5, lane = tid & 31;
    const int gid = lane >> 2, tig = lane & 3;
    const int ty = (wid >> 1) * 32;              // warp M offset (t)
    const int tx = (wid & 1) * 64;               // warp N offset (a)
    const int tt = blockIdx.x, b = blockIdx.y;

    for (int i = tid; i < DA_; i += 256) bw[i] = make_float2(b1[i], w2[i]);

    const unsigned char* xsrc0 = g_xp[0][b][tt][0];
    const unsigned char* xsrc1 = g_xp[1][b][tt][0];

    float c[2][8][4];
#pragma unroll
    for (int mt = 0; mt < 2; mt++)
#pragma unroll
        for (int nt = 0; nt < 8; nt++)
#pragma unroll
            for (int k = 0; k < 4; k++) c[mt][nt][k] = 0.f;
    float s[2][2] = {{0.f, 0.f}, {0.f, 0.f}};

    // issue cp.async copies for iteration `it`
    auto issue = [&](int it) {
        const int nc = it / NKC, kc = it - nc * NKC;
        const unsigned char* srcs[4] = {
            xsrc0 + (size_t)kc * TILE_BYTES,
            xsrc1 + (size_t)kc * TILE_BYTES,
            g_wp[0][nc][kc],
            g_wp[1][nc][kc]
        };
        unsigned char* dst = bufs + (it & 1) * BUF_BYTES;
#pragma unroll
        for (int j = 0; j < 8; j++) {
            const int g    = tid + j * 256;
            const int tile = g >> 9, gi = g & 511;
            const int row  = gi >> 2, col = gi & 3;
            cpa16(smem_u32(dst + tile * TILE_SMEM + row * ROW_PITCH + col * 16),
                  srcs[tile] + gi * 16);
        }
    };

    issue(0); CP_COMMIT();

    const int NIT = NNC * NKC;
    for (int it = 0; it < NIT; it++) {
        if (it + 1 < NIT) {
            issue(it + 1); CP_COMMIT();
            asm volatile("cp.async.wait_group 1;" ::: "memory");
        } else {
            asm volatile("cp.async.wait_group 0;" ::: "memory");
        }
        __syncthreads();

        const unsigned char* buf = bufs + (it & 1) * BUF_BYTES;
        const unsigned char* Ah = buf;
        const unsigned char* Al = buf + TILE_SMEM;
        const unsigned char* Bh = buf + 2 * TILE_SMEM;
        const unsigned char* Bl = buf + 3 * TILE_SMEM;

#pragma unroll
        for (int kt = 0; kt < 2; kt++) {
            uint32_t ah[2][4], al[2][4];
#pragma unroll
            for (int mt = 0; mt < 2; mt++) {
                const unsigned char* pa = Ah + (ty + mt * 16 + gid) * ROW_PITCH + kt * 32 + tig * 4;
                ah[mt][0] = *(const uint32_t*)pa;
                ah[mt][1] = *(const uint32_t*)(pa + 8 * ROW_PITCH);
                ah[mt][2] = *(const uint32_t*)(pa + 16);
                ah[mt][3] = *(const uint32_t*)(pa + 8 * ROW_PITCH + 16);
                const unsigned char* pl = Al + (ty + mt * 16 + gid) * ROW_PITCH + kt * 32 + tig * 4;
                al[mt][0] = *(const uint32_t*)pl;
                al[mt][1] = *(const uint32_t*)(pl + 8 * ROW_PITCH);
                al[mt][2] = *(const uint32_t*)(pl + 16);
                al[mt][3] = *(const uint32_t*)(pl + 8 * ROW_PITCH + 16);
            }
#pragma unroll
            for (int nt = 0; nt < 8; nt++) {
                const unsigned char* pb = Bh + (tx + nt * 8 + gid) * ROW_PITCH + kt * 32 + tig * 4;
                const uint32_t bh0 = *(const uint32_t*)pb;
                const uint32_t bh1 = *(const uint32_t*)(pb + 16);
                const unsigned char* pq = Bl + (tx + nt * 8 + gid) * ROW_PITCH + kt * 32 + tig * 4;
                const uint32_t bl0 = *(const uint32_t*)pq;
                const uint32_t bl1 = *(const uint32_t*)(pq + 16);
#pragma unroll
                for (int mt = 0; mt < 2; mt++) {
                    mma_bf16(c[mt][nt], ah[mt], bh0, bh1);   // hi*hi
                    mma_bf16(c[mt][nt], ah[mt], bl0, bl1);   // hi*lo
                    mma_bf16(c[mt][nt], al[mt], bh0, bh1);   // lo*hi
                }
            }
        }

        // end of K for this n-chunk? -> epilogue into score regs, reset accums
        const int nc = it / NKC, kc = it - nc * NKC;
        if (kc == NKC - 1) {
#pragma unroll
            for (int mt = 0; mt < 2; mt++)
#pragma unroll
                for (int nt = 0; nt < 8; nt++) {
                    const int a = nc * 128 + tx + nt * 8 + 2 * tig;
                    const float2 q0 = bw[a], q1 = bw[a + 1];
                    const float h0 = fmaxf(c[mt][nt][0] + q0.x, 0.f);
                    const float h1 = fmaxf(c[mt][nt][1] + q1.x, 0.f);
                    const float h2 = fmaxf(c[mt][nt][2] + q0.x, 0.f);
                    const float h3 = fmaxf(c[mt][nt][3] + q1.x, 0.f);
                    s[mt][0] = fmaf(h0, q0.y, fmaf(h1, q1.y, s[mt][0]));
                    s[mt][1] = fmaf(h2, q0.y, fmaf(h3, q1.y, s[mt][1]));
                    c[mt][nt][0] = c[mt][nt][1] = c[mt][nt][2] = c[mt][nt][3] = 0.f;
                }
        }
        __syncthreads();
    }

    // reduce scores: over tig lanes, then over the 2 N-warps
#pragma unroll
    for (int mt = 0; mt < 2; mt++)
#pragma unroll
        for (int r = 0; r < 2; r++) {
            float v = s[mt][r];
            v += __shfl_xor_sync(0xffffffffu, v, 1);
            v += __shfl_xor_sync(0xffffffffu, v, 2);
            if (tig == 0)
                red[(wid & 1) * 128 + ty + mt * 16 + r * 8 + gid] = v;
        }
    __syncthreads();
    if (tid < 128) {
        const float sc = red[tid] + red[128 + tid];
        const int t = tt * 128 + tid;
        if (t < T_) g_scores[b * 1024 + t] = sc;
    }
}

// ===========================================================================
// Softmax over T per batch
// ===========================================================================
__device__ __forceinline__ float warpMax(float v) {
#pragma unroll
    for (int o = 16; o; o >>= 1) v = fmaxf(v, __shfl_xor_sync(0xffffffffu, v, o));
    return v;
}
__device__ __forceinline__ float warpSum(float v) {
#pragma unroll
    for (int o = 16; o; o >>= 1) v += __shfl_xor_sync(0xffffffffu, v, o);
    return v;
}

__global__ void k_softmax(float* __restrict__ Aout)
{
    const int b = blockIdx.x;
    const int tid = threadIdx.x;
    const int lane = tid & 31, wid = tid >> 5;
    __shared__ float sm[32];
    __shared__ float bcast;

    const bool valid = tid < T_;
    float sc = valid ? g_scores[b * 1024 + tid] : 0.f;

    float v = valid ? sc : -CUDART_INF_F;
    v = warpMax(v);
    if (lane == 0) sm[wid] = v;
    __syncthreads();
    if (wid == 0) {
        float w = sm[lane];
        w = warpMax(w);
        if (lane == 0) bcast = w;
    }
    __syncthreads();
    const float m = bcast;

    float e = valid ? expf(sc - m) : 0.f;
    float ss = warpSum(e);
    if (lane == 0) sm[wid] = ss;
    __syncthreads();
    if (wid == 0) {
        float w = sm[lane];
        w = warpSum(w);
        if (lane == 0) bcast = w;
    }
    __syncthreads();

    if (valid) Aout[(size_t)b * T_ + tid] = e / bcast;
}

// ===========================================================================
// Weighted stats
// ===========================================================================
__global__ __launch_bounds__(256)
void k_stats(const float* __restrict__ x, const float* __restrict__ Ain,
             float* __restrict__ out)
{
    __shared__ __align__(16) float sA[1000];
    const int b  = blockIdx.y;
    const int d0 = blockIdx.x * 8;

    for (int i = threadIdx.x; i < T_; i += blockDim.x) sA[i] = Ain[(size_t)b * T_ + i];
    __syncthreads();

    const int w = threadIdx.x >> 5, lane = threadIdx.x & 31;
    const int d = d0 + w;
    if (d >= D_) return;

    const float* row = x + ((size_t)b * D_ + d) * T_;
    float e = 0.f, q = 0.f;
#pragma unroll
    for (int j = 0; j < 8; j++) {
        int idx = j * 128 + lane * 4;
        if (idx < T_) {
            float4 xv = *reinterpret_cast<const float4*>(row + idx);
            float4 av = *reinterpret_cast<const float4*>(&sA[idx]);
            e = fmaf(xv.x, av.x, e); q = fmaf(xv.x * xv.x, av.x, q);
            e = fmaf(xv.y, av.y, e); q = fmaf(xv.y * xv.y, av.y, q);
            e = fmaf(xv.z, av.z, e); q = fmaf(xv.z * xv.z, av.z, q);
            e = fmaf(xv.w, av.w, e); q = fmaf(xv.w * xv.w, av.w, q);
        }
    }
    e = warpSum(e);
    q = warpSum(q);
    if (lane == 0) {
        float var = q - e * e;
        var = var > 0.f ? var : 0.f;
        out[(size_t)b * 3000 + d]        = e;
        out[(size_t)b * 3000 + 1500 + d] = sqrtf(var + 1e-5f);
    }
}

// ===========================================================================
// Launcher
// ===========================================================================
extern "C" void kernel_launch(void* const* d_in, const int* in_sizes, int n_in,
                              void* d_out, int out_size)
{
    const float* x  = (const float*)d_in[0];
    const float* w1 = (const float*)d_in[1];
    const float* b1 = (const float*)d_in[2];
    const float* w2 = (const float*)d_in[3];
    // d_in[4] = bias_2: softmax-invariant, does not affect A or layer_out.

    float* A_out = (float*)d_out;            // [64, 1000]
    float* L_out = (float*)d_out + B_ * T_;  // [64, 3000]

    cudaFuncSetAttribute(k_score_mma, cudaFuncAttributeMaxDynamicSharedMemorySize, SMEM_TOTAL);

    dim3 gx(8, B_);
    k_prep_x<<<gx, 256>>>(x);

    dim3 gw(NNC, NKC);
    k_prep_w<<<gw, 256>>>(w1);

    dim3 gs(8, B_);
    k_score_mma<<<gs, 256, SMEM_TOTAL>>>(b1, w2);

    k_softmax<<<B_, 1024>>>(A_out);

    dim3 g3((D_ + 7) / 8, B_);
    k_stats<<<g3, 256>>>(x, A_out, L_out);
}

// round 4
// speedup vs baseline: 2.9226x; 2.0901x over previous
#include <cuda_runtime.h>
#include <cuda_bf16.h>
#include <math_constants.h>
#include <cstdint>

// Problem constants
#define B_  64
#define D_  1500
#define T_  1000
#define DA_ 512

#define NKC 47             // K chunks of 32 d (47*32 = 1504 >= 1500)
#define NNC 4              // N chunks of 128 a
#define TILE_BYTES 16384   // 128 rows x 32 tf32 words (128B/row)
#define BUF_BYTES (2 * TILE_BYTES)        // A,B = 32768
#define SMEM_TOTAL (5120 + 2 * BUF_BYTES) // 70656

// ===========================================================================
// Scratch (__device__ globals — allocation-guard-safe)
// ===========================================================================
__device__ unsigned char g_xp[B_][8][NKC][TILE_BYTES];   // x^T tf32 tiles [t][k]
__device__ unsigned char g_wp[NNC][NKC][TILE_BYTES];     // w1^T tf32 tiles [n][k]
__device__ float g_scores[B_ * 1024];

// ===========================================================================
// Helpers
// ===========================================================================
__device__ __forceinline__ uint32_t smem_u32(const void* p) {
    uint32_t a;
    asm("{ .reg .u64 t; cvta.to.shared.u64 t, %1; cvt.u32.u64 %0, t; }" : "=r"(a) : "l"(p));
    return a;
}
__device__ __forceinline__ void cpa16(uint32_t dst, const void* src) {
    asm volatile("cp.async.cg.shared.global [%0], [%1], 16;" :: "r"(dst), "l"(src));
}
#define CP_COMMIT() asm volatile("cp.async.commit_group;" ::: "memory")

__device__ __forceinline__ uint32_t to_tf32(float f) {
    uint32_t r;
    asm("cvt.rna.tf32.f32 %0, %1;" : "=r"(r) : "f"(f));
    return r;
}

__device__ __forceinline__ void mma_tf32(float c[4], const uint32_t a[4],
                                         uint32_t b0, uint32_t b1) {
    asm volatile(
        "mma.sync.aligned.m16n8k8.row.col.f32.tf32.tf32.f32 "
        "{%0,%1,%2,%3}, {%4,%5,%6,%7}, {%8,%9}, {%0,%1,%2,%3};"
        : "+f"(c[0]), "+f"(c[1]), "+f"(c[2]), "+f"(c[3])
        : "r"(a[0]), "r"(a[1]), "r"(a[2]), "r"(a[3]), "r"(b0), "r"(b1));
}

// ===========================================================================
// Prep x: [b][d][t] fp32 -> tf32 tiles [b][tt][kc][t(128)][k(32 words)]
// ===========================================================================
__global__ __launch_bounds__(256)
void k_prep_x(const float* __restrict__ x)
{
    __shared__ float st[32][132];
    const int tt = blockIdx.x, b = blockIdx.y;
    const int tid = threadIdx.x, wid = tid >> 5, lane = tid & 31;
    const float* xb = x + (size_t)b * D_ * T_;

    for (int kc = 0; kc < NKC; kc++) {
#pragma unroll
        for (int i = 0; i < 4; i++) {
            const int dr = i * 8 + wid;
            const int d  = kc * 32 + dr;
            const int t  = tt * 128 + lane * 4;
            float4 v = make_float4(0.f, 0.f, 0.f, 0.f);
            if (d < D_ && t < T_) v = *(const float4*)(xb + (size_t)d * T_ + t);
            *(float4*)&st[dr][lane * 4] = v;
        }
        __syncthreads();
        {
            const int t = tid >> 1, h = tid & 1;
            uint32_t w[16];
#pragma unroll
            for (int i = 0; i < 16; i++) w[i] = to_tf32(st[h * 16 + i][t]);
            unsigned char* dp = g_xp[b][tt][kc] + t * 128 + h * 64;
            *(uint4*)dp        = make_uint4(w[0],  w[1],  w[2],  w[3]);
            *(uint4*)(dp + 16) = make_uint4(w[4],  w[5],  w[6],  w[7]);
            *(uint4*)(dp + 32) = make_uint4(w[8],  w[9],  w[10], w[11]);
            *(uint4*)(dp + 48) = make_uint4(w[12], w[13], w[14], w[15]);
        }
        __syncthreads();
    }
}

// ===========================================================================
// Prep w1: [d][a] fp32 -> tf32 tiles [nc][kc][n(128)][k(32 words)]
// ===========================================================================
__global__ __launch_bounds__(256)
void k_prep_w(const float* __restrict__ w1)
{
    __shared__ float st[32][132];
    const int nc = blockIdx.x, kc = blockIdx.y;
    const int tid = threadIdx.x, wid = tid >> 5, lane = tid & 31;

#pragma unroll
    for (int i = 0; i < 4; i++) {
        const int dr = i * 8 + wid;
        const int d  = kc * 32 + dr;
        const int n  = nc * 128 + lane * 4;
        float4 v = make_float4(0.f, 0.f, 0.f, 0.f);
        if (d < D_) v = *(const float4*)(w1 + (size_t)d * DA_ + n);
        *(float4*)&st[dr][lane * 4] = v;
    }
    __syncthreads();
    {
        const int n = tid >> 1, h = tid & 1;
        uint32_t w[16];
#pragma unroll
        for (int i = 0; i < 16; i++) w[i] = to_tf32(st[h * 16 + i][n]);
        unsigned char* dp = g_wp[nc][kc] + n * 128 + h * 64;
        *(uint4*)dp        = make_uint4(w[0],  w[1],  w[2],  w[3]);
        *(uint4*)(dp + 16) = make_uint4(w[4],  w[5],  w[6],  w[7]);
        *(uint4*)(dp + 32) = make_uint4(w[8],  w[9],  w[10], w[11]);
        *(uint4*)(dp + 48) = make_uint4(w[12], w[13], w[14], w[15]);
    }
}

// ===========================================================================
// k_score_mma: per CTA (b, 128-t tile) -> scores[t], single-pass TF32 HMMA.
// Smem tile layout: row r (128B), 16B-chunk c stored at c ^ (r & 7).
// ===========================================================================
__global__ __launch_bounds__(256, 2)
void k_score_mma(const float* __restrict__ b1, const float* __restrict__ w2)
{
    extern __shared__ __align__(16) unsigned char smem[];
    float2* bw  = (float2*)smem;                 // [512] (b1, w2)
    float*  red = (float*)(smem + 4096);         // [2][128]
    unsigned char* bufs = smem + 5120;           // double buffer

    const int tid = threadIdx.x;
    const int wid = tid >> 5, lane = tid & 31;
    const int gid = lane >> 2, tig = lane & 3;
    const int ty = (wid >> 1) * 32;              // warp M offset (t)
    const int tx = (wid & 1) * 64;               // warp N offset (a)
    const int tt = blockIdx.x, b = blockIdx.y;

    for (int i = tid; i < DA_; i += 256) bw[i] = make_float2(b1[i], w2[i]);

    const unsigned char* xsrc = g_xp[b][tt][0];

    float c[2][8][4];
#pragma unroll
    for (int mt = 0; mt < 2; mt++)
#pragma unroll
        for (int nt = 0; nt < 8; nt++)
#pragma unroll
            for (int k = 0; k < 4; k++) c[mt][nt][k] = 0.f;
    float s[2][2] = {{0.f, 0.f}, {0.f, 0.f}};

    auto issue = [&](int it) {
        const int nc = it / NKC, kc = it - nc * NKC;
        const unsigned char* srcs[2] = {
            xsrc + (size_t)kc * TILE_BYTES,
            g_wp[nc][kc]
        };
        unsigned char* dst = bufs + (it & 1) * BUF_BYTES;
#pragma unroll
        for (int j = 0; j < 8; j++) {
            const int g    = tid + j * 256;
            const int tile = g >> 10, gi = g & 1023;
            const int row  = gi >> 3, cch = gi & 7;
            cpa16(smem_u32(dst + tile * TILE_BYTES + row * 128 + ((cch ^ (row & 7)) << 4)),
                  srcs[tile] + gi * 16);
        }
    };

    issue(0); CP_COMMIT();

    const int NIT = NNC * NKC;
    for (int it = 0; it < NIT; it++) {
        if (it + 1 < NIT) {
            issue(it + 1); CP_COMMIT();
            asm volatile("cp.async.wait_group 1;" ::: "memory");
        } else {
            asm volatile("cp.async.wait_group 0;" ::: "memory");
        }
        __syncthreads();

        const unsigned char* buf = bufs + (it & 1) * BUF_BYTES;
        const unsigned char* At = buf;
        const unsigned char* Bt = buf + TILE_BYTES;

        // swizzled 32-bit fragment load: row r, 16B-chunk index cc, word tig
        auto lda = [&](const unsigned char* base, int r, int cc) -> uint32_t {
            return *(const uint32_t*)(base + r * 128 + (((cc) ^ (r & 7)) << 4) + tig * 4);
        };

#pragma unroll
        for (int kt = 0; kt < 4; kt++) {
            const int c0 = 2 * kt, c1 = 2 * kt + 1;
            uint32_t af[2][4];
#pragma unroll
            for (int mt = 0; mt < 2; mt++) {
                const int r = ty + mt * 16 + gid;
                af[mt][0] = lda(At, r,     c0);
                af[mt][1] = lda(At, r + 8, c0);
                af[mt][2] = lda(At, r,     c1);
                af[mt][3] = lda(At, r + 8, c1);
            }
#pragma unroll
            for (int nt = 0; nt < 8; nt++) {
                const int rb = tx + nt * 8 + gid;
                const uint32_t b0 = lda(Bt, rb, c0);
                const uint32_t bq = lda(Bt, rb, c1);
#pragma unroll
                for (int mt = 0; mt < 2; mt++)
                    mma_tf32(c[mt][nt], af[mt], b0, bq);
            }
        }

        // end of K for this n-chunk -> fold into score regs, reset accums
        const int nc = it / NKC, kc = it - nc * NKC;
        if (kc == NKC - 1) {
#pragma unroll
            for (int mt = 0; mt < 2; mt++)
#pragma unroll
                for (int nt = 0; nt < 8; nt++) {
                    const int a = nc * 128 + tx + nt * 8 + 2 * tig;
                    const float2 q0 = bw[a], q1 = bw[a + 1];
                    const float h0 = fmaxf(c[mt][nt][0] + q0.x, 0.f);
                    const float h1 = fmaxf(c[mt][nt][1] + q1.x, 0.f);
                    const float h2 = fmaxf(c[mt][nt][2] + q0.x, 0.f);
                    const float h3 = fmaxf(c[mt][nt][3] + q1.x, 0.f);
                    s[mt][0] = fmaf(h0, q0.y, fmaf(h1, q1.y, s[mt][0]));
                    s[mt][1] = fmaf(h2, q0.y, fmaf(h3, q1.y, s[mt][1]));
                    c[mt][nt][0] = c[mt][nt][1] = c[mt][nt][2] = c[mt][nt][3] = 0.f;
                }
        }
        __syncthreads();
    }

    // reduce scores: over tig lanes, then over the 2 N-warps
#pragma unroll
    for (int mt = 0; mt < 2; mt++)
#pragma unroll
        for (int r = 0; r < 2; r++) {
            float v = s[mt][r];
            v += __shfl_xor_sync(0xffffffffu, v, 1);
            v += __shfl_xor_sync(0xffffffffu, v, 2);
            if (tig == 0)
                red[(wid & 1) * 128 + ty + mt * 16 + r * 8 + gid] = v;
        }
    __syncthreads();
    if (tid < 128) {
        const float sc = red[tid] + red[128 + tid];
        const int t = tt * 128 + tid;
        if (t < T_) g_scores[b * 1024 + t] = sc;
    }
}

// ===========================================================================
// Softmax over T per batch
// ===========================================================================
__device__ __forceinline__ float warpMax(float v) {
#pragma unroll
    for (int o = 16; o; o >>= 1) v = fmaxf(v, __shfl_xor_sync(0xffffffffu, v, o));
    return v;
}
__device__ __forceinline__ float warpSum(float v) {
#pragma unroll
    for (int o = 16; o; o >>= 1) v += __shfl_xor_sync(0xffffffffu, v, o);
    return v;
}

__global__ void k_softmax(float* __restrict__ Aout)
{
    const int b = blockIdx.x;
    const int tid = threadIdx.x;
    const int lane = tid & 31, wid = tid >> 5;
    __shared__ float sm[32];
    __shared__ float bcast;

    const bool valid = tid < T_;
    float sc = valid ? g_scores[b * 1024 + tid] : 0.f;

    float v = valid ? sc : -CUDART_INF_F;
    v = warpMax(v);
    if (lane == 0) sm[wid] = v;
    __syncthreads();
    if (wid == 0) {
        float w = sm[lane];
        w = warpMax(w);
        if (lane == 0) bcast = w;
    }
    __syncthreads();
    const float m = bcast;

    float e = valid ? expf(sc - m) : 0.f;
    float ss = warpSum(e);
    if (lane == 0) sm[wid] = ss;
    __syncthreads();
    if (wid == 0) {
        float w = sm[lane];
        w = warpSum(w);
        if (lane == 0) bcast = w;
    }
    __syncthreads();

    if (valid) Aout[(size_t)b * T_ + tid] = e / bcast;
}

// ===========================================================================
// Weighted stats
// ===========================================================================
__global__ __launch_bounds__(256)
void k_stats(const float* __restrict__ x, const float* __restrict__ Ain,
             float* __restrict__ out)
{
    __shared__ __align__(16) float sA[1000];
    const int b  = blockIdx.y;
    const int d0 = blockIdx.x * 8;

    for (int i = threadIdx.x; i < T_; i += blockDim.x) sA[i] = Ain[(size_t)b * T_ + i];
    __syncthreads();

    const int w = threadIdx.x >> 5, lane = threadIdx.x & 31;
    const int d = d0 + w;
    if (d >= D_) return;

    const float* row = x + ((size_t)b * D_ + d) * T_;
    float e = 0.f, q = 0.f;
#pragma unroll
    for (int j = 0; j < 8; j++) {
        int idx = j * 128 + lane * 4;
        if (idx < T_) {
            float4 xv = *reinterpret_cast<const float4*>(row + idx);
            float4 av = *reinterpret_cast<const float4*>(&sA[idx]);
            e = fmaf(xv.x, av.x, e); q = fmaf(xv.x * xv.x, av.x, q);
            e = fmaf(xv.y, av.y, e); q = fmaf(xv.y * xv.y, av.y, q);
            e = fmaf(xv.z, av.z, e); q = fmaf(xv.z * xv.z, av.z, q);
            e = fmaf(xv.w, av.w, e); q = fmaf(xv.w * xv.w, av.w, q);
        }
    }
    e = warpSum(e);
    q = warpSum(q);
    if (lane == 0) {
        float var = q - e * e;
        var = var > 0.f ? var : 0.f;
        out[(size_t)b * 3000 + d]        = e;
        out[(size_t)b * 3000 + 1500 + d] = sqrtf(var + 1e-5f);
    }
}

// ===========================================================================
// Launcher
// ===========================================================================
extern "C" void kernel_launch(void* const* d_in, const int* in_sizes, int n_in,
                              void* d_out, int out_size)
{
    const float* x  = (const float*)d_in[0];
    const float* w1 = (const float*)d_in[1];
    const float* b1 = (const float*)d_in[2];
    const float* w2 = (const float*)d_in[3];
    // d_in[4] = bias_2: softmax-invariant, does not affect A or layer_out.

    float* A_out = (float*)d_out;            // [64, 1000]
    float* L_out = (float*)d_out + B_ * T_;  // [64, 3000]

    cudaFuncSetAttribute(k_score_mma, cudaFuncAttributeMaxDynamicSharedMemorySize, SMEM_TOTAL);

    dim3 gx(8, B_);
    k_prep_x<<<gx, 256>>>(x);

    dim3 gw(NNC, NKC);
    k_prep_w<<<gw, 256>>>(w1);

    dim3 gs(8, B_);
    k_score_mma<<<gs, 256, SMEM_TOTAL>>>(b1, w2);

    k_softmax<<<B_, 1024>>>(A_out);

    dim3 g3((D_ + 7) / 8, B_);
    k_stats<<<g3, 256>>>(x, A_out, L_out);
}

// round 5
// speedup vs baseline: 3.1825x; 1.0889x over previous
#include <cuda_runtime.h>
#include <cuda_bf16.h>
#include <math_constants.h>
#include <cstdint>

// Problem constants
#define B_  64
#define D_  1500
#define T_  1000
#define DA_ 512

#define NKC 47                  // K chunks of 32 d (47*32 = 1504 >= 1500)
#define NNC 2                   // N chunks of 256 a
#define NIT (NNC * NKC)         // 94
#define A_TILE 16384            // 128t x 32k tf32, fragment-major
#define B_TILE 32768            // 256a x 32k tf32, fragment-major
#define STAGE  (A_TILE + B_TILE)          // 49152
#define OFF_RED 4096
#define OFF_BUF 6144
#define SMEM_TOTAL (OFF_BUF + 4 * STAGE)  // 202752

// ===========================================================================
// Scratch (__device__ globals)
// ===========================================================================
__device__ unsigned char g_xp[B_][8][NKC][A_TILE];   // x^T tiles, fragment-major
__device__ unsigned char g_wp[NNC][NKC][B_TILE];     // w1^T tiles, fragment-major
__device__ float g_scores[B_ * 1024];

// ===========================================================================
// Helpers
// ===========================================================================
__device__ __forceinline__ uint32_t smem_u32(const void* p) {
    uint32_t a;
    asm("{ .reg .u64 t; cvta.to.shared.u64 t, %1; cvt.u32.u64 %0, t; }" : "=r"(a) : "l"(p));
    return a;
}
__device__ __forceinline__ void cpa16(uint32_t dst, const void* src) {
    asm volatile("cp.async.cg.shared.global [%0], [%1], 16;" :: "r"(dst), "l"(src));
}
#define CP_COMMIT() asm volatile("cp.async.commit_group;" ::: "memory")

__device__ __forceinline__ uint32_t to_tf32(float f) {
    uint32_t r;
    asm("cvt.rna.tf32.f32 %0, %1;" : "=r"(r) : "f"(f));
    return r;
}

__device__ __forceinline__ void mma_tf32(float c[4], const uint4& a,
                                         uint32_t b0, uint32_t b1) {
    asm volatile(
        "mma.sync.aligned.m16n8k8.row.col.f32.tf32.tf32.f32 "
        "{%0,%1,%2,%3}, {%4,%5,%6,%7}, {%8,%9}, {%0,%1,%2,%3};"
        : "+f"(c[0]), "+f"(c[1]), "+f"(c[2]), "+f"(c[3])
        : "r"(a.x), "r"(a.y), "r"(a.z), "r"(a.w), "r"(b0), "r"(b1));
}

// ===========================================================================
// Prep x: [b][d][t] fp32 -> fragment-major tf32 A tiles
//   entry e in [0,1024): mb=e>>7, kt=(e>>5)&3, lane=e&31 (gid=lane>>2,tig=lane&3)
//   uint4 = { A[mb*16+gid][kt*8+tig], A[+8][k], A[row][k+4], A[+8][k+4] }
// ===========================================================================
__global__ __launch_bounds__(256)
void k_prep_x(const float* __restrict__ x)
{
    __shared__ float st[32][136];
    const int tt = blockIdx.x, b = blockIdx.y;
    const int tid = threadIdx.x, wid = tid >> 5, lane = tid & 31;
    const float* xb = x + (size_t)b * D_ * T_;

    for (int kc = 0; kc < NKC; kc++) {
#pragma unroll
        for (int i = 0; i < 4; i++) {
            const int dr = i * 8 + wid;
            const int d  = kc * 32 + dr;
            const int t  = tt * 128 + lane * 4;
            float4 v = make_float4(0.f, 0.f, 0.f, 0.f);
            if (d < D_ && t < T_) v = *(const float4*)(xb + (size_t)d * T_ + t);
            *(float4*)&st[dr][lane * 4] = v;
        }
        __syncthreads();
#pragma unroll
        for (int i = 0; i < 4; i++) {
            const int e   = tid + i * 256;
            const int mb  = e >> 7, rem = e & 127;
            const int kt  = rem >> 5, ln = rem & 31;
            const int gid = ln >> 2, tig = ln & 3;
            const int tl  = mb * 16 + gid;
            const int kl  = kt * 8 + tig;
            uint4 w;
            w.x = to_tf32(st[kl][tl]);
            w.y = to_tf32(st[kl][tl + 8]);
            w.z = to_tf32(st[kl + 4][tl]);
            w.w = to_tf32(st[kl + 4][tl + 8]);
            *(uint4*)(g_xp[b][tt][kc] + e * 16) = w;
        }
        __syncthreads();
    }
}

// ===========================================================================
// Prep w1: [d][a] fp32 -> fragment-major tf32 B tiles (per nc: 256 a)
//   entry e in [0,4096): nb=e>>7, kt=(e>>5)&3, lane=e&31
//   uint2 = { B[nb*8+gid][kt*8+tig], B[row][k+4] }
// ===========================================================================
__global__ __launch_bounds__(256)
void k_prep_w(const float* __restrict__ w1)
{
    __shared__ float st[32][264];
    const int nc = blockIdx.x, kc = blockIdx.y;
    const int tid = threadIdx.x;

#pragma unroll
    for (int i = 0; i < 8; i++) {
        const int idx = tid + i * 256;
        const int row = idx >> 6;               // 0..31 (d within chunk)
        const int col = (idx & 63) * 4;         // 0..252
        const int d   = kc * 32 + row;
        float4 v = make_float4(0.f, 0.f, 0.f, 0.f);
        if (d < D_) v = *(const float4*)(w1 + (size_t)d * DA_ + nc * 256 + col);
        *(float4*)&st[row][col] = v;
    }
    __syncthreads();
#pragma unroll
    for (int i = 0; i < 16; i++) {
        const int e   = tid + i * 256;
        const int nb  = e >> 7, rem = e & 127;
        const int kt  = rem >> 5, ln = rem & 31;
        const int gid = ln >> 2, tig = ln & 3;
        const int nl  = nb * 8 + gid;
        const int kl  = kt * 8 + tig;
        uint2 w;
        w.x = to_tf32(st[kl][nl]);
        w.y = to_tf32(st[kl + 4][nl]);
        *(uint2*)(g_wp[nc][kc] + e * 8) = w;
    }
}

// ===========================================================================
// k_score_mma: CTA = (b, 128-t tile) x 256a per pass, 8 warps (2M x 4N),
// warp tile 64x64, 4-stage cp.async pipeline, fragment-major smem (no swizzle).
// ===========================================================================
__global__ __launch_bounds__(256)
void k_score_mma(const float* __restrict__ b1, const float* __restrict__ w2)
{
    extern __shared__ __align__(16) unsigned char smem[];
    float2* bw  = (float2*)smem;                 // [512] (b1, w2)
    float*  red = (float*)(smem + OFF_RED);      // [4][128]
    unsigned char* bufs = smem + OFF_BUF;        // 4-stage

    const int tid  = threadIdx.x;
    const int wid  = tid >> 5, lane = tid & 31;
    const int gid  = lane >> 2, tig = lane & 3;
    const int mw   = wid >> 2;                   // 0..1  (M half, 64 t each)
    const int nw   = wid & 3;                    // 0..3  (N quarter, 64 a each)
    const int tt   = blockIdx.x, b = blockIdx.y;

    for (int i = tid; i < DA_; i += 256) bw[i] = make_float2(b1[i], w2[i]);

    const unsigned char* xsrc = g_xp[b][tt][0];

    float c[4][8][4];
#pragma unroll
    for (int mt = 0; mt < 4; mt++)
#pragma unroll
        for (int nt = 0; nt < 8; nt++)
#pragma unroll
            for (int k = 0; k < 4; k++) c[mt][nt][k] = 0.f;
    float s[4][2];
#pragma unroll
    for (int mt = 0; mt < 4; mt++) { s[mt][0] = 0.f; s[mt][1] = 0.f; }

    auto issue = [&](int it) {
        const int nc = it / NKC, kc = it - nc * NKC;
        const unsigned char* Asrc = xsrc + (size_t)kc * A_TILE;
        const unsigned char* Bsrc = g_wp[nc][kc];
        unsigned char* dst = bufs + (size_t)(it & 3) * STAGE;
#pragma unroll
        for (int i = 0; i < 4; i++) {           // A: 1024 chunks
            const int g = tid + i * 256;
            cpa16(smem_u32(dst + g * 16), Asrc + g * 16);
        }
#pragma unroll
        for (int i = 0; i < 8; i++) {           // B: 2048 chunks
            const int g = tid + i * 256;
            cpa16(smem_u32(dst + A_TILE + g * 16), Bsrc + g * 16);
        }
    };

    issue(0); CP_COMMIT();
    issue(1); CP_COMMIT();
    issue(2); CP_COMMIT();

    for (int it = 0; it < NIT; it++) {
        if (it <= NIT - 3)      asm volatile("cp.async.wait_group 2;" ::: "memory");
        else if (it == NIT - 2) asm volatile("cp.async.wait_group 1;" ::: "memory");
        else                    asm volatile("cp.async.wait_group 0;" ::: "memory");
        __syncthreads();

        if (it + 3 < NIT) { issue(it + 3); CP_COMMIT(); }

        const unsigned char* stg = bufs + (size_t)(it & 3) * STAGE;
        const unsigned char* At = stg;
        const unsigned char* Bt = stg + A_TILE;

#pragma unroll
        for (int kt = 0; kt < 4; kt++) {
            uint4 af[4];
#pragma unroll
            for (int mt = 0; mt < 4; mt++)
                af[mt] = *(const uint4*)(At + ((((mw * 4 + mt) * 4 + kt) * 32 + lane) << 4));
#pragma unroll
            for (int nt = 0; nt < 8; nt++) {
                const uint2 bf = *(const uint2*)(Bt + ((((nw * 8 + nt) * 4 + kt) * 32 + lane) << 3));
#pragma unroll
                for (int mt = 0; mt < 4; mt++)
                    mma_tf32(c[mt][nt], af[mt], bf.x, bf.y);
            }
        }

        // end of K for this n-chunk -> fold into score regs, reset accums
        const int nc = it / NKC, kc = it - nc * NKC;
        if (kc == NKC - 1) {
#pragma unroll
            for (int mt = 0; mt < 4; mt++)
#pragma unroll
                for (int nt = 0; nt < 8; nt++) {
                    const int a = nc * 256 + nw * 64 + nt * 8 + 2 * tig;
                    const float2 q0 = bw[a], q1 = bw[a + 1];
                    const float h0 = fmaxf(c[mt][nt][0] + q0.x, 0.f);
                    const float h1 = fmaxf(c[mt][nt][1] + q1.x, 0.f);
                    const float h2 = fmaxf(c[mt][nt][2] + q0.x, 0.f);
                    const float h3 = fmaxf(c[mt][nt][3] + q1.x, 0.f);
                    s[mt][0] = fmaf(h0, q0.y, fmaf(h1, q1.y, s[mt][0]));
                    s[mt][1] = fmaf(h2, q0.y, fmaf(h3, q1.y, s[mt][1]));
                    c[mt][nt][0] = c[mt][nt][1] = c[mt][nt][2] = c[mt][nt][3] = 0.f;
                }
        }
        __syncthreads();
    }

    // reduce: over tig lanes (shfl), then over the 4 N-warps (smem)
#pragma unroll
    for (int mt = 0; mt < 4; mt++)
#pragma unroll
        for (int r = 0; r < 2; r++) {
            float v = s[mt][r];
            v += __shfl_xor_sync(0xffffffffu, v, 1);
            v += __shfl_xor_sync(0xffffffffu, v, 2);
            if (tig == 0)
                red[nw * 128 + mw * 64 + mt * 16 + r * 8 + gid] = v;
        }
    __syncthreads();
    if (tid < 128) {
        const float sc = red[tid] + red[128 + tid] + red[256 + tid] + red[384 + tid];
        const int t = tt * 128 + tid;
        if (t < T_) g_scores[b * 1024 + t] = sc;
    }
}

// ===========================================================================
// Softmax over T per batch
// ===========================================================================
__device__ __forceinline__ float warpMax(float v) {
#pragma unroll
    for (int o = 16; o; o >>= 1) v = fmaxf(v, __shfl_xor_sync(0xffffffffu, v, o));
    return v;
}
__device__ __forceinline__ float warpSum(float v) {
#pragma unroll
    for (int o = 16; o; o >>= 1) v += __shfl_xor_sync(0xffffffffu, v, o);
    return v;
}

__global__ void k_softmax(float* __restrict__ Aout)
{
    const int b = blockIdx.x;
    const int tid = threadIdx.x;
    const int lane = tid & 31, wid = tid >> 5;
    __shared__ float sm[32];
    __shared__ float bcast;

    const bool valid = tid < T_;
    float sc = valid ? g_scores[b * 1024 + tid] : 0.f;

    float v = valid ? sc : -CUDART_INF_F;
    v = warpMax(v);
    if (lane == 0) sm[wid] = v;
    __syncthreads();
    if (wid == 0) {
        float w = sm[lane];
        w = warpMax(w);
        if (lane == 0) bcast = w;
    }
    __syncthreads();
    const float m = bcast;

    float e = valid ? expf(sc - m) : 0.f;
    float ss = warpSum(e);
    if (lane == 0) sm[wid] = ss;
    __syncthreads();
    if (wid == 0) {
        float w = sm[lane];
        w = warpSum(w);
        if (lane == 0) bcast = w;
    }
    __syncthreads();

    if (valid) Aout[(size_t)b * T_ + tid] = e / bcast;
}

// ===========================================================================
// Weighted stats
// ===========================================================================
__global__ __launch_bounds__(256)
void k_stats(const float* __restrict__ x, const float* __restrict__ Ain,
             float* __restrict__ out)
{
    __shared__ __align__(16) float sA[1000];
    const int b  = blockIdx.y;
    const int d0 = blockIdx.x * 8;

    for (int i = threadIdx.x; i < T_; i += blockDim.x) sA[i] = Ain[(size_t)b * T_ + i];
    __syncthreads();

    const int w = threadIdx.x >> 5, lane = threadIdx.x & 31;
    const int d = d0 + w;
    if (d >= D_) return;

    const float* row = x + ((size_t)b * D_ + d) * T_;
    float e = 0.f, q = 0.f;
#pragma unroll
    for (int j = 0; j < 8; j++) {
        int idx = j * 128 + lane * 4;
        if (idx < T_) {
            float4 xv = *reinterpret_cast<const float4*>(row + idx);
            float4 av = *reinterpret_cast<const float4*>(&sA[idx]);
            e = fmaf(xv.x, av.x, e); q = fmaf(xv.x * xv.x, av.x, q);
            e = fmaf(xv.y, av.y, e); q = fmaf(xv.y * xv.y, av.y, q);
            e = fmaf(xv.z, av.z, e); q = fmaf(xv.z * xv.z, av.z, q);
            e = fmaf(xv.w, av.w, e); q = fmaf(xv.w * xv.w, av.w, q);
        }
    }
    e = warpSum(e);
    q = warpSum(q);
    if (lane == 0) {
        float var = q - e * e;
        var = var > 0.f ? var : 0.f;
        out[(size_t)b * 3000 + d]        = e;
        out[(size_t)b * 3000 + 1500 + d] = sqrtf(var + 1e-5f);
    }
}

// ===========================================================================
// Launcher
// ===========================================================================
extern "C" void kernel_launch(void* const* d_in, const int* in_sizes, int n_in,
                              void* d_out, int out_size)
{
    const float* x  = (const float*)d_in[0];
    const float* w1 = (const float*)d_in[1];
    const float* b1 = (const float*)d_in[2];
    const float* w2 = (const float*)d_in[3];
    // d_in[4] = bias_2: softmax-invariant, does not affect A or layer_out.

    float* A_out = (float*)d_out;            // [64, 1000]
    float* L_out = (float*)d_out + B_ * T_;  // [64, 3000]

    cudaFuncSetAttribute(k_score_mma, cudaFuncAttributeMaxDynamicSharedMemorySize, SMEM_TOTAL);

    dim3 gx(8, B_);
    k_prep_x<<<gx, 256>>>(x);

    dim3 gw(NNC, NKC);
    k_prep_w<<<gw, 256>>>(w1);

    dim3 gs(8, B_);
    k_score_mma<<<gs, 256, SMEM_TOTAL>>>(b1, w2);

    k_softmax<<<B_, 1024>>>(A_out);

    dim3 g3((D_ + 7) / 8, B_);
    k_stats<<<g3, 256>>>(x, A_out, L_out);
}

// round 6
// speedup vs baseline: 5.1109x; 1.6060x over previous
#include <cuda_runtime.h>
#include <cuda_fp16.h>
#include <math_constants.h>
#include <cstdint>

// Problem constants
#define B_  64
#define D_  1500
#define T_  1000
#define DA_ 512

#define NKC 47                  // K chunks of 32 d (47*32 = 1504 >= 1500)
#define NNC 2                   // N chunks of 256 a
#define NIT (NNC * NKC)         // 94
#define A_TILE 8192             // 128t x 32k fp16, fragment-major
#define B_TILE 16384            // 256a x 32k fp16, fragment-major
#define STAGE  (A_TILE + B_TILE)          // 24576
#define OFF_RED 4096
#define OFF_BUF 6144
#define SMEM_TOTAL (OFF_BUF + 4 * STAGE)  // 104448

// ===========================================================================
// Scratch (__device__ globals)
// ===========================================================================
__device__ unsigned char g_xp[B_][8][NKC][A_TILE];   // x^T tiles, fragment-major fp16
__device__ unsigned char g_wp[NNC][NKC][B_TILE];     // w1^T tiles, fragment-major fp16
__device__ float g_scores[B_ * 1024];

// ===========================================================================
// Helpers
// ===========================================================================
__device__ __forceinline__ uint32_t smem_u32(const void* p) {
    uint32_t a;
    asm("{ .reg .u64 t; cvta.to.shared.u64 t, %1; cvt.u32.u64 %0, t; }" : "=r"(a) : "l"(p));
    return a;
}
__device__ __forceinline__ void cpa16(uint32_t dst, const void* src) {
    asm volatile("cp.async.cg.shared.global [%0], [%1], 16;" :: "r"(dst), "l"(src));
}
#define CP_COMMIT() asm volatile("cp.async.commit_group;" ::: "memory")

__device__ __forceinline__ uint32_t packh2(float lo, float hi) {
    __half2 h = __floats2half2_rn(lo, hi);
    return *(uint32_t*)&h;
}

__device__ __forceinline__ void mma_f16(float c[4], const uint4& a,
                                        uint32_t b0, uint32_t b1) {
    asm volatile(
        "mma.sync.aligned.m16n8k16.row.col.f32.f16.f16.f32 "
        "{%0,%1,%2,%3}, {%4,%5,%6,%7}, {%8,%9}, {%0,%1,%2,%3};"
        : "+f"(c[0]), "+f"(c[1]), "+f"(c[2]), "+f"(c[3])
        : "r"(a.x), "r"(a.y), "r"(a.z), "r"(a.w), "r"(b0), "r"(b1));
}

// ===========================================================================
// Prep x: [b][d][t] fp32 -> fragment-major fp16 A tiles
//   entry e in [0,512): mb=e>>6, kt=(e>>5)&1, lane=e&31 (gid=lane>>2,tig=lane&3)
//   uint4 = {A[tl][k..k+1], A[tl+8][k..k+1], A[tl][k+8..k+9], A[tl+8][k+8..k+9]}
//   where tl=mb*16+gid, k=kt*16+2*tig (A[t][d], fp16 pairs packed low-first)
// ===========================================================================
__global__ __launch_bounds__(256)
void k_prep_x(const float* __restrict__ x)
{
    __shared__ float st[32][132];
    const int tt = blockIdx.x, b = blockIdx.y;
    const int tid = threadIdx.x, wid = tid >> 5, lane = tid & 31;
    const float* xb = x + (size_t)b * D_ * T_;

    for (int kc = 0; kc < NKC; kc++) {
#pragma unroll
        for (int i = 0; i < 4; i++) {
            const int dr = i * 8 + wid;
            const int d  = kc * 32 + dr;
            const int t  = tt * 128 + lane * 4;
            float4 v = make_float4(0.f, 0.f, 0.f, 0.f);
            if (d < D_ && t < T_) v = *(const float4*)(xb + (size_t)d * T_ + t);
            *(float4*)&st[dr][lane * 4] = v;
        }
        __syncthreads();
#pragma unroll
        for (int i = 0; i < 2; i++) {
            const int e   = tid + i * 256;
            const int mb  = e >> 6, rem = e & 63;
            const int kt  = rem >> 5, ln = rem & 31;
            const int gid = ln >> 2, tig = ln & 3;
            const int tl  = mb * 16 + gid;
            const int kl  = kt * 16 + 2 * tig;
            uint4 w;
            w.x = packh2(st[kl][tl],         st[kl + 1][tl]);
            w.y = packh2(st[kl][tl + 8],     st[kl + 1][tl + 8]);
            w.z = packh2(st[kl + 8][tl],     st[kl + 9][tl]);
            w.w = packh2(st[kl + 8][tl + 8], st[kl + 9][tl + 8]);
            *(uint4*)(g_xp[b][tt][kc] + e * 16) = w;
        }
        __syncthreads();
    }
}

// ===========================================================================
// Prep w1: [d][a] fp32 -> fragment-major fp16 B tiles (per nc: 256 a)
//   entry e in [0,2048): nb=e>>6, kt=(e>>5)&1, lane=e&31
//   uint2 = {B[k..k+1][nl], B[k+8..k+9][nl]}, nl=nb*8+gid, k=kt*16+2*tig
// ===========================================================================
__global__ __launch_bounds__(256)
void k_prep_w(const float* __restrict__ w1)
{
    __shared__ float st[32][260];
    const int nc = blockIdx.x, kc = blockIdx.y;
    const int tid = threadIdx.x;

#pragma unroll
    for (int i = 0; i < 8; i++) {
        const int idx = tid + i * 256;
        const int row = idx >> 6;               // 0..31 (d within chunk)
        const int col = (idx & 63) * 4;         // 0..252
        const int d   = kc * 32 + row;
        float4 v = make_float4(0.f, 0.f, 0.f, 0.f);
        if (d < D_) v = *(const float4*)(w1 + (size_t)d * DA_ + nc * 256 + col);
        *(float4*)&st[row][col] = v;
    }
    __syncthreads();
#pragma unroll
    for (int i = 0; i < 8; i++) {
        const int e   = tid + i * 256;
        const int nb  = e >> 6, rem = e & 63;
        const int kt  = rem >> 5, ln = rem & 31;
        const int gid = ln >> 2, tig = ln & 3;
        const int nl  = nb * 8 + gid;
        const int kl  = kt * 16 + 2 * tig;
        uint2 w;
        w.x = packh2(st[kl][nl],     st[kl + 1][nl]);
        w.y = packh2(st[kl + 8][nl], st[kl + 9][nl]);
        *(uint2*)(g_wp[nc][kc] + e * 8) = w;
    }
}

// ===========================================================================
// k_score_mma: CTA = (b, 128-t tile) x 256a per pass, 8 warps (2M x 4N),
// warp tile 64x64, 4-stage cp.async pipeline, fragment-major smem, fp16 MMA.
// ===========================================================================
__global__ __launch_bounds__(256)
void k_score_mma(const float* __restrict__ b1, const float* __restrict__ w2)
{
    extern __shared__ __align__(16) unsigned char smem[];
    float2* bw  = (float2*)smem;                 // [512] (b1, w2)
    float*  red = (float*)(smem + OFF_RED);      // [4][128]
    unsigned char* bufs = smem + OFF_BUF;        // 4-stage

    const int tid  = threadIdx.x;
    const int wid  = tid >> 5, lane = tid & 31;
    const int gid  = lane >> 2, tig = lane & 3;
    const int mw   = wid >> 2;                   // 0..1  (M half, 64 t each)
    const int nw   = wid & 3;                    // 0..3  (N quarter, 64 a each)
    const int tt   = blockIdx.x, b = blockIdx.y;

    for (int i = tid; i < DA_; i += 256) bw[i] = make_float2(b1[i], w2[i]);

    const unsigned char* xsrc = g_xp[b][tt][0];

    float c[4][8][4];
#pragma unroll
    for (int mt = 0; mt < 4; mt++)
#pragma unroll
        for (int nt = 0; nt < 8; nt++)
#pragma unroll
            for (int k = 0; k < 4; k++) c[mt][nt][k] = 0.f;
    float s[4][2];
#pragma unroll
    for (int mt = 0; mt < 4; mt++) { s[mt][0] = 0.f; s[mt][1] = 0.f; }

    auto issue = [&](int it) {
        const int nc = it / NKC, kc = it - nc * NKC;
        const unsigned char* Asrc = xsrc + (size_t)kc * A_TILE;
        const unsigned char* Bsrc = g_wp[nc][kc];
        unsigned char* dst = bufs + (size_t)(it & 3) * STAGE;
#pragma unroll
        for (int i = 0; i < 2; i++) {           // A: 512 chunks
            const int g = tid + i * 256;
            cpa16(smem_u32(dst + g * 16), Asrc + g * 16);
        }
#pragma unroll
        for (int i = 0; i < 4; i++) {           // B: 1024 chunks
            const int g = tid + i * 256;
            cpa16(smem_u32(dst + A_TILE + g * 16), Bsrc + g * 16);
        }
    };

    issue(0); CP_COMMIT();
    issue(1); CP_COMMIT();
    issue(2); CP_COMMIT();

    for (int it = 0; it < NIT; it++) {
        if (it <= NIT - 3)      asm volatile("cp.async.wait_group 2;" ::: "memory");
        else if (it == NIT - 2) asm volatile("cp.async.wait_group 1;" ::: "memory");
        else                    asm volatile("cp.async.wait_group 0;" ::: "memory");
        __syncthreads();

        if (it + 3 < NIT) { issue(it + 3); CP_COMMIT(); }

        const unsigned char* stg = bufs + (size_t)(it & 3) * STAGE;
        const unsigned char* At = stg;
        const unsigned char* Bt = stg + A_TILE;

#pragma unroll
        for (int kt = 0; kt < 2; kt++) {
            uint4 af[4];
#pragma unroll
            for (int mt = 0; mt < 4; mt++)
                af[mt] = *(const uint4*)(At + ((((mw * 4 + mt) * 2 + kt) * 32 + lane) << 4));
#pragma unroll
            for (int nt = 0; nt < 8; nt++) {
                const uint2 bf = *(const uint2*)(Bt + ((((nw * 8 + nt) * 2 + kt) * 32 + lane) << 3));
#pragma unroll
                for (int mt = 0; mt < 4; mt++)
                    mma_f16(c[mt][nt], af[mt], bf.x, bf.y);
            }
        }

        // end of K for this n-chunk -> fold into score regs, reset accums
        const int nc = it / NKC, kc = it - nc * NKC;
        if (kc == NKC - 1) {
#pragma unroll
            for (int mt = 0; mt < 4; mt++)
#pragma unroll
                for (int nt = 0; nt < 8; nt++) {
                    const int a = nc * 256 + nw * 64 + nt * 8 + 2 * tig;
                    const float2 q0 = bw[a], q1 = bw[a + 1];
                    const float h0 = fmaxf(c[mt][nt][0] + q0.x, 0.f);
                    const float h1 = fmaxf(c[mt][nt][1] + q1.x, 0.f);
                    const float h2 = fmaxf(c[mt][nt][2] + q0.x, 0.f);
                    const float h3 = fmaxf(c[mt][nt][3] + q1.x, 0.f);
                    s[mt][0] = fmaf(h0, q0.y, fmaf(h1, q1.y, s[mt][0]));
                    s[mt][1] = fmaf(h2, q0.y, fmaf(h3, q1.y, s[mt][1]));
                    c[mt][nt][0] = c[mt][nt][1] = c[mt][nt][2] = c[mt][nt][3] = 0.f;
                }
        }
        __syncthreads();
    }

    // reduce: over tig lanes (shfl), then over the 4 N-warps (smem)
#pragma unroll
    for (int mt = 0; mt < 4; mt++)
#pragma unroll
        for (int r = 0; r < 2; r++) {
            float v = s[mt][r];
            v += __shfl_xor_sync(0xffffffffu, v, 1);
            v += __shfl_xor_sync(0xffffffffu, v, 2);
            if (tig == 0)
                red[nw * 128 + mw * 64 + mt * 16 + r * 8 + gid] = v;
        }
    __syncthreads();
    if (tid < 128) {
        const float sc = red[tid] + red[128 + tid] + red[256 + tid] + red[384 + tid];
        const int t = tt * 128 + tid;
        if (t < T_) g_scores[b * 1024 + t] = sc;
    }
}

// ===========================================================================
// Softmax over T per batch
// ===========================================================================
__device__ __forceinline__ float warpMax(float v) {
#pragma unroll
    for (int o = 16; o; o >>= 1) v = fmaxf(v, __shfl_xor_sync(0xffffffffu, v, o));
    return v;
}
__device__ __forceinline__ float warpSum(float v) {
#pragma unroll
    for (int o = 16; o; o >>= 1) v += __shfl_xor_sync(0xffffffffu, v, o);
    return v;
}

__global__ void k_softmax(float* __restrict__ Aout)
{
    const int b = blockIdx.x;
    const int tid = threadIdx.x;
    const int lane = tid & 31, wid = tid >> 5;
    __shared__ float sm[32];
    __shared__ float bcast;

    const bool valid = tid < T_;
    float sc = valid ? g_scores[b * 1024 + tid] : 0.f;

    float v = valid ? sc : -CUDART_INF_F;
    v = warpMax(v);
    if (lane == 0) sm[wid] = v;
    __syncthreads();
    if (wid == 0) {
        float w = sm[lane];
        w = warpMax(w);
        if (lane == 0) bcast = w;
    }
    __syncthreads();
    const float m = bcast;

    float e = valid ? expf(sc - m) : 0.f;
    float ss = warpSum(e);
    if (lane == 0) sm[wid] = ss;
    __syncthreads();
    if (wid == 0) {
        float w = sm[lane];
        w = warpSum(w);
        if (lane == 0) bcast = w;
    }
    __syncthreads();

    if (valid) Aout[(size_t)b * T_ + tid] = e / bcast;
}

// ===========================================================================
// Weighted stats
// ===========================================================================
__global__ __launch_bounds__(256)
void k_stats(const float* __restrict__ x, const float* __restrict__ Ain,
             float* __restrict__ out)
{
    __shared__ __align__(16) float sA[1000];
    const int b  = blockIdx.y;
    const int d0 = blockIdx.x * 8;

    for (int i = threadIdx.x; i < T_; i += blockDim.x) sA[i] = Ain[(size_t)b * T_ + i];
    __syncthreads();

    const int w = threadIdx.x >> 5, lane = threadIdx.x & 31;
    const int d = d0 + w;
    if (d >= D_) return;

    const float* row = x + ((size_t)b * D_ + d) * T_;
    float e = 0.f, q = 0.f;
#pragma unroll
    for (int j = 0; j < 8; j++) {
        int idx = j * 128 + lane * 4;
        if (idx < T_) {
            float4 xv = *reinterpret_cast<const float4*>(row + idx);
            float4 av = *reinterpret_cast<const float4*>(&sA[idx]);
            e = fmaf(xv.x, av.x, e); q = fmaf(xv.x * xv.x, av.x, q);
            e = fmaf(xv.y, av.y, e); q = fmaf(xv.y * xv.y, av.y, q);
            e = fmaf(xv.z, av.z, e); q = fmaf(xv.z * xv.z, av.z, q);
            e = fmaf(xv.w, av.w, e); q = fmaf(xv.w * xv.w, av.w, q);
        }
    }
    e = warpSum(e);
    q = warpSum(q);
    if (lane == 0) {
        float var = q - e * e;
        var = var > 0.f ? var : 0.f;
        out[(size_t)b * 3000 + d]        = e;
        out[(size_t)b * 3000 + 1500 + d] = sqrtf(var + 1e-5f);
    }
}

// ===========================================================================
// Launcher
// ===========================================================================
extern "C" void kernel_launch(void* const* d_in, const int* in_sizes, int n_in,
                              void* d_out, int out_size)
{
    const float* x  = (const float*)d_in[0];
    const float* w1 = (const float*)d_in[1];
    const float* b1 = (const float*)d_in[2];
    const float* w2 = (const float*)d_in[3];
    // d_in[4] = bias_2: softmax-invariant, does not affect A or layer_out.

    float* A_out = (float*)d_out;            // [64, 1000]
    float* L_out = (float*)d_out + B_ * T_;  // [64, 3000]

    cudaFuncSetAttribute(k_score_mma, cudaFuncAttributeMaxDynamicSharedMemorySize, SMEM_TOTAL);

    dim3 gx(8, B_);
    k_prep_x<<<gx, 256>>>(x);

    dim3 gw(NNC, NKC);
    k_prep_w<<<gw, 256>>>(w1);

    dim3 gs(8, B_);
    k_score_mma<<<gs, 256, SMEM_TOTAL>>>(b1, w2);

    k_softmax<<<B_, 1024>>>(A_out);

    dim3 g3((D_ + 7) / 8, B_);
    k_stats<<<g3, 256>>>(x, A_out, L_out);
}